// round 14
// baseline (speedup 1.0000x reference)
#include <cuda_runtime.h>
#include <math.h>

#define BB   128
#define NN   8192
#define MM   64
#define HID  512
#define OUTC 256
#define REPR 70
#define SEQW 63
#define R1   6656                         // colsum row split: 24 warps do [0,R1), ctrl warps do [R1,NN)
#define SMEM_DYN (4*NN*sizeof(float))     // n2, dkw, dkr, dae : 128 KB

#define NB() asm volatile("bar.sync 1, 256;" ::: "memory")

__device__ __forceinline__ float lrelu(float v){ return (v>0.f)? v : 0.01f*v; }

// block-wide sum, 1024 threads (32 warps)
__device__ __forceinline__ float bredsum1024(float v, float* sred){
    const int lane = threadIdx.x & 31, wid = threadIdx.x >> 5;
    #pragma unroll
    for (int o=16;o>0;o>>=1) v += __shfl_xor_sync(0xffffffffu, v, o);
    if (lane==0) sred[wid]=v;
    __syncthreads();
    if (wid==0){
        float w = sred[lane];
        #pragma unroll
        for (int o=16;o>0;o>>=1) w += __shfl_xor_sync(0xffffffffu, w, o);
        if (lane==0) sred[0]=w;
    }
    __syncthreads();
    float r = sred[0];
    __syncthreads();
    return r;
}

// ctrl-group (first 256 threads) sum via named barrier 1
__device__ __forceinline__ float credsum256(float v, float* cred){
    const int lane = threadIdx.x & 31, wid = threadIdx.x >> 5;  // wid 0..7
    #pragma unroll
    for (int o=16;o>0;o>>=1) v += __shfl_xor_sync(0xffffffffu, v, o);
    if (lane==0) cred[wid]=v;
    NB();
    float r = cred[0]+cred[1]+cred[2]+cred[3]+cred[4]+cred[5]+cred[6]+cred[7];
    NB();
    return r;
}

// ---------------- THE kernel: one block per batch, everything fused ----------------
__global__ void __launch_bounds__(1024) k_mega(
    const float* __restrict__ bank,
    const float* __restrict__ x,
    const float* __restrict__ wrp, const float* __restrict__ wwp,
    const float* __restrict__ W0, const float* __restrict__ b0,
    const float* __restrict__ W1, const float* __restrict__ b1,
    const float* __restrict__ Wc, const float* __restrict__ bc,
    const float* __restrict__ Wr, const float* __restrict__ br,
    const float* __restrict__ Ww, const float* __restrict__ bw,
    const float* __restrict__ Wea, const float* __restrict__ bea,
    const float* __restrict__ Wsp, const float* __restrict__ bsp,
    const float* __restrict__ Wo,  const float* __restrict__ bo,
    float* __restrict__ out)
{
    extern __shared__ float sm[];
    float* s_n2  = sm;
    float* s_dkw = sm + NN;
    float* s_dkr = sm + 2*NN;
    float* s_dae = sm + 3*NN;

    __shared__ float xs[SEQW+1], h0s[HID], h1s[HID], cs_[OUTC];
    __shared__ float rr[REPR], rw[REPR];
    __shared__ float sred[32], cred[8], scs[MM], om[MM], seqs[HID];
    __shared__ float s_kw[MM], s_kr[MM], s_ae[MM], pp[16];
    __shared__ float ma[MM], eas[2*MM];

    const int b = blockIdx.x;
    const int t = threadIdx.x;
    const int lane = t & 31, wid = t >> 5;
    const size_t base = (size_t)b * NN;

    if (t < MM) scs[t] = 0.f;
    __syncthreads();

    // ===================== Phase A: ctrl+tail-colsum (t<256) || colsum (t>=256) =====================
    if (t < 256){
        if (t < SEQW+1) xs[t] = x[b*(SEQW+1)+t];
        NB();
        {   // layer 0: 64 -> 512
            float a0 = b0[t], a1 = b0[t+256];
            #pragma unroll
            for (int i=0;i<SEQW+1;i++){
                float v = xs[i];
                a0 = fmaf(v, W0[i*HID + t],     a0);
                a1 = fmaf(v, W0[i*HID + t+256], a1);
            }
            h0s[t] = lrelu(a0); h0s[t+256] = lrelu(a1);
        }
        NB();
        {   // layer 1: 512 -> 512
            float a0 = b1[t], a1 = b1[t+256];
            #pragma unroll 16
            for (int i=0;i<HID;i++){
                float v = h0s[i];
                a0 = fmaf(v, W1[i*HID + t],     a0);
                a1 = fmaf(v, W1[i*HID + t+256], a1);
            }
            h1s[t] = lrelu(a0); h1s[t+256] = lrelu(a1);
        }
        NB();
        {   // ctrl: 512 -> 256
            float a0 = bc[t];
            #pragma unroll 16
            for (int i=0;i<HID;i++)
                a0 = fmaf(h1s[i], Wc[i*OUTC + t], a0);
            cs_[t] = lrelu(a0);
        }
        NB();
        if (t < REPR){
            float a = br[t];
            #pragma unroll 16
            for (int i=0;i<OUTC;i++) a = fmaf(cs_[i], Wr[i*REPR + t], a);
            rr[t] = a;
        } else if (t >= 128 && t < 128+REPR){
            const int j = t-128;
            float a = bw[j];
            #pragma unroll 16
            for (int i=0;i<OUTC;i++) a = fmaf(cs_[i], Ww[i*REPR + j], a);
            rw[j] = a;
        }
        NB();
        float vr = 0.f, vw = 0.f;
        if (t < MM){
            vr = rr[t]; vw = rw[t];
            s_kr[t] = vr; s_kw[t] = vw;
        }
        float nr  = credsum256(vr*vr, cred);
        float nw_ = credsum256(vw*vw, cred);
        float sr=0.f, sw=0.f;
        for (int n=t; n<NN; n+=256){ sr += wrp[base+n]; sw += wwp[base+n]; }
        sr = credsum256(sr, cred);
        sw = credsum256(sw, cred);
        if (t==0){
            pp[12]=sqrtf(nr); pp[13]=sqrtf(nw_);
            pp[14]=1.f/sr;    pp[15]=1.f/sw;
            pp[0] = fmaxf(rr[64],0.f)+1e-8f;
            pp[1] = 1.f/(1.f+__expf(-rr[65]));
            {
                float m = fmaxf(rr[66], fmaxf(rr[67], rr[68]));
                float e0=__expf(rr[66]-m), e1=__expf(rr[67]-m), e2=__expf(rr[68]-m);
                float s=e0+e1+e2;
                pp[2]=e0/s; pp[3]=e1/s; pp[4]=e2/s;
            }
            pp[5] = fmaxf(rr[69],0.f)+1.f;
            pp[6] = fmaxf(rw[64],0.f)+1e-8f;
            pp[7] = 1.f/(1.f+__expf(-rw[65]));
            {
                float m = fmaxf(rw[66], fmaxf(rw[67], rw[68]));
                float e0=__expf(rw[66]-m), e1=__expf(rw[67]-m), e2=__expf(rw[68]-m);
                float s=e0+e1+e2;
                pp[8]=e0/s; pp[9]=e1/s; pp[10]=e2/s;
            }
            pp[11] = fmaxf(rw[69],0.f)+1.f;
        }
        // ---- tail colsum: ctrl warps (wid 0..7) stream rows [R1, NN) ----
        {
            const int sub16 = lane & 15, half = lane >> 4;
            const float* bp = bank + base*MM + sub16*4;
            float4 cs = make_float4(0.f,0.f,0.f,0.f);
            // 1536 rows, 8 warps * 2 rows per step = 16 rows/step -> 96 steps = 24 iters of 4
            for (int it=0; it<24; it++){
                #pragma unroll
                for (int j=0;j<4;j++){
                    int row = R1 + (it*4+j)*16 + wid*2 + half;
                    float4 v = *reinterpret_cast<const float4*>(bp + (size_t)row*MM);
                    cs.x += v.x; cs.y += v.y; cs.z += v.z; cs.w += v.w;
                }
            }
            cs.x += __shfl_xor_sync(0xffffffffu, cs.x, 16);
            cs.y += __shfl_xor_sync(0xffffffffu, cs.y, 16);
            cs.z += __shfl_xor_sync(0xffffffffu, cs.z, 16);
            cs.w += __shfl_xor_sync(0xffffffffu, cs.w, 16);
            if (half == 0){
                atomicAdd(&scs[sub16*4+0], cs.x);
                atomicAdd(&scs[sub16*4+1], cs.y);
                atomicAdd(&scs[sub16*4+2], cs.z);
                atomicAdd(&scs[sub16*4+3], cs.w);
            }
        }
    } else {
        // colsum rows [0, R1) with 768 threads (warps 8..31)
        const int wc2 = wid - 8;            // 0..23
        const int sub16 = lane & 15, half = lane >> 4;
        const float* bp = bank + base*MM + sub16*4;
        float4 cs = make_float4(0.f,0.f,0.f,0.f);
        // 6656 rows, 24 warps * 2 rows/step = 48 rows/step -> 138.67 steps -> 35 iters of 4 w/ bound
        for (int it=0; it<35; it++){
            #pragma unroll
            for (int j=0;j<4;j++){
                int row = (it*4+j)*48 + wc2*2 + half;
                if (row < R1){
                    float4 v = *reinterpret_cast<const float4*>(bp + (size_t)row*MM);
                    cs.x += v.x; cs.y += v.y; cs.z += v.z; cs.w += v.w;
                }
            }
        }
        cs.x += __shfl_xor_sync(0xffffffffu, cs.x, 16);
        cs.y += __shfl_xor_sync(0xffffffffu, cs.y, 16);
        cs.z += __shfl_xor_sync(0xffffffffu, cs.z, 16);
        cs.w += __shfl_xor_sync(0xffffffffu, cs.w, 16);
        if (half == 0){
            atomicAdd(&scs[sub16*4+0], cs.x);
            atomicAdd(&scs[sub16*4+1], cs.y);
            atomicAdd(&scs[sub16*4+2], cs.z);
            atomicAdd(&scs[sub16*4+3], cs.w);
        }
    }
    __syncthreads();

    // ===================== ea =====================
    if (t < MM) ma[t] = scs[t] * (1.f/(float)NN);
    __syncthreads();
    if (t < MM) scs[t] = 0.f;     // re-zero for the weighted-read phase
    if (t < 2*MM){
        float acc = bea[t];
        #pragma unroll 8
        for (int i=0;i<MM;i++) acc = fmaf(ma[i],   Wea[i*(2*MM)+t],      acc);
        #pragma unroll 8
        for (int i=0;i<MM;i++) acc = fmaf(s_kw[i], Wea[(MM+i)*(2*MM)+t], acc);
        eas[t] = acc;
    }
    __syncthreads();
    float aev = 0.f, krv = 0.f;
    if (t < MM){
        float e = 1.f/(1.f+__expf(-eas[t]));
        aev = eas[MM+t]-e;
        s_ae[t] = aev;
        krv = s_kr[t];
    }
    const float ae2  = bredsum1024(aev*aev,  sred);
    const float aekr = bredsum1024(aev*krv, sred);

    // ===================== Phase 1: one stream -> n2, dkw, dkr, dae (smem), 2 rows/thread ===========
    {
        const int sub8 = lane & 7, rowg = lane >> 3;
        const int coff = sub8*8;
        const float4 kwA = *reinterpret_cast<const float4*>(&s_kw[coff]);
        const float4 kwB = *reinterpret_cast<const float4*>(&s_kw[coff+4]);
        const float4 krA = *reinterpret_cast<const float4*>(&s_kr[coff]);
        const float4 krB = *reinterpret_cast<const float4*>(&s_kr[coff+4]);
        const float4 aeA = *reinterpret_cast<const float4*>(&s_ae[coff]);
        const float4 aeB = *reinterpret_cast<const float4*>(&s_ae[coff+4]);
        const float* bp = bank + base*MM + coff;
        // 32 iters: warp covers 8 rows/iter (thread: rows ra, ra+4)
        for (int it=0; it<32; it++){
            const int ra = it*256 + wid*8 + rowg;
            const int rb = ra + 4;
            const float4 va0 = *reinterpret_cast<const float4*>(bp + (size_t)ra*MM);
            const float4 va1 = *reinterpret_cast<const float4*>(bp + (size_t)ra*MM + 4);
            const float4 vb0 = *reinterpret_cast<const float4*>(bp + (size_t)rb*MM);
            const float4 vb1 = *reinterpret_cast<const float4*>(bp + (size_t)rb*MM + 4);
            float dwA=0.f, dkA=0.f, daA=0.f, nnA=0.f;
            float dwB=0.f, dkB=0.f, daB=0.f, nnB=0.f;
            dwA=fmaf(va0.x,kwA.x,dwA); dwA=fmaf(va0.y,kwA.y,dwA); dwA=fmaf(va0.z,kwA.z,dwA); dwA=fmaf(va0.w,kwA.w,dwA);
            dwA=fmaf(va1.x,kwB.x,dwA); dwA=fmaf(va1.y,kwB.y,dwA); dwA=fmaf(va1.z,kwB.z,dwA); dwA=fmaf(va1.w,kwB.w,dwA);
            dkA=fmaf(va0.x,krA.x,dkA); dkA=fmaf(va0.y,krA.y,dkA); dkA=fmaf(va0.z,krA.z,dkA); dkA=fmaf(va0.w,krA.w,dkA);
            dkA=fmaf(va1.x,krB.x,dkA); dkA=fmaf(va1.y,krB.y,dkA); dkA=fmaf(va1.z,krB.z,dkA); dkA=fmaf(va1.w,krB.w,dkA);
            daA=fmaf(va0.x,aeA.x,daA); daA=fmaf(va0.y,aeA.y,daA); daA=fmaf(va0.z,aeA.z,daA); daA=fmaf(va0.w,aeA.w,daA);
            daA=fmaf(va1.x,aeB.x,daA); daA=fmaf(va1.y,aeB.y,daA); daA=fmaf(va1.z,aeB.z,daA); daA=fmaf(va1.w,aeB.w,daA);
            nnA=fmaf(va0.x,va0.x,nnA); nnA=fmaf(va0.y,va0.y,nnA); nnA=fmaf(va0.z,va0.z,nnA); nnA=fmaf(va0.w,va0.w,nnA);
            nnA=fmaf(va1.x,va1.x,nnA); nnA=fmaf(va1.y,va1.y,nnA); nnA=fmaf(va1.z,va1.z,nnA); nnA=fmaf(va1.w,va1.w,nnA);
            dwB=fmaf(vb0.x,kwA.x,dwB); dwB=fmaf(vb0.y,kwA.y,dwB); dwB=fmaf(vb0.z,kwA.z,dwB); dwB=fmaf(vb0.w,kwA.w,dwB);
            dwB=fmaf(vb1.x,kwB.x,dwB); dwB=fmaf(vb1.y,kwB.y,dwB); dwB=fmaf(vb1.z,kwB.z,dwB); dwB=fmaf(vb1.w,kwB.w,dwB);
            dkB=fmaf(vb0.x,krA.x,dkB); dkB=fmaf(vb0.y,krA.y,dkB); dkB=fmaf(vb0.z,krA.z,dkB); dkB=fmaf(vb0.w,krA.w,dkB);
            dkB=fmaf(vb1.x,krB.x,dkB); dkB=fmaf(vb1.y,krB.y,dkB); dkB=fmaf(vb1.z,krB.z,dkB); dkB=fmaf(vb1.w,krB.w,dkB);
            daB=fmaf(vb0.x,aeA.x,daB); daB=fmaf(vb0.y,aeA.y,daB); daB=fmaf(vb0.z,aeA.z,daB); daB=fmaf(vb0.w,aeA.w,daB);
            daB=fmaf(vb1.x,aeB.x,daB); daB=fmaf(vb1.y,aeB.y,daB); daB=fmaf(vb1.z,aeB.z,daB); daB=fmaf(vb1.w,aeB.w,daB);
            nnB=fmaf(vb0.x,vb0.x,nnB); nnB=fmaf(vb0.y,vb0.y,nnB); nnB=fmaf(vb0.z,vb0.z,nnB); nnB=fmaf(vb0.w,vb0.w,nnB);
            nnB=fmaf(vb1.x,vb1.x,nnB); nnB=fmaf(vb1.y,vb1.y,nnB); nnB=fmaf(vb1.z,vb1.z,nnB); nnB=fmaf(vb1.w,vb1.w,nnB);
            #pragma unroll
            for (int o=1;o<8;o<<=1){
                dwA += __shfl_xor_sync(0xffffffffu, dwA, o);
                dkA += __shfl_xor_sync(0xffffffffu, dkA, o);
                daA += __shfl_xor_sync(0xffffffffu, daA, o);
                nnA += __shfl_xor_sync(0xffffffffu, nnA, o);
                dwB += __shfl_xor_sync(0xffffffffu, dwB, o);
                dkB += __shfl_xor_sync(0xffffffffu, dkB, o);
                daB += __shfl_xor_sync(0xffffffffu, daB, o);
                nnB += __shfl_xor_sync(0xffffffffu, nnB, o);
            }
            if (sub8 == 0){
                s_dkw[ra]=dwA; s_dkr[ra]=dkA; s_dae[ra]=daA; s_n2[ra]=nnA;
                s_dkw[rb]=dwB; s_dkr[rb]=dkB; s_dae[rb]=daB; s_n2[rb]=nnB;
            }
        }
    }
    __syncthreads();

    float ww_loc[8];
    float S;

    // ===================== write addressing (in s_dkw, shifted softmax) =====================
    {
        const float beta=pp[6], gg=pp[7], s0=pp[8], s1=pp[9], s2=pp[10], gamma=pp[11];
        const float nk=pp[13], invs=pp[15];
        float lsum=0.f;
        #pragma unroll
        for (int i=0;i<8;i++){
            int n = t + i*1024;
            float cosv = __fdividef(s_dkw[n], fmaxf(sqrtf(s_n2[n])*nk, 1e-8f));
            float e = __expf(beta*cosv - beta);
            s_dkw[n]=e; lsum+=e;
        }
        const float invsum = __fdividef(1.f, bredsum1024(lsum, sred));
        #pragma unroll
        for (int i=0;i<8;i++){
            int n=t+i*1024;
            float wc = s_dkw[n]*invsum;
            s_dkw[n] = gg*wc + (1.f-gg)*wwp[base+n]*invs;
        }
        __syncthreads();
        float lps=0.f;
        #pragma unroll
        for (int i=0;i<8;i++){
            int n=t+i*1024;
            float ws = s0*s_dkw[(n+NN-1)&(NN-1)] + s1*s_dkw[n] + s2*s_dkw[(n+1)&(NN-1)];
            float wp = __powf(ws, gamma);
            ww_loc[i]=wp; lps+=wp;
        }
        const float invp = __fdividef(1.f, bredsum1024(lps, sred));
        #pragma unroll
        for (int i=0;i<8;i++) ww_loc[i] *= invp;
    }

    // ===================== read addressing (in s_dkr; rank-1 new_bank algebra) =====================
    {
        const float beta=pp[0], gg=pp[1], s0=pp[2], s1=pp[3], s2=pp[4], gamma=pp[5];
        const float nk=pp[12], invs=pp[14];
        float lsum=0.f;
        #pragma unroll
        for (int i=0;i<8;i++){
            int n = t + i*1024;
            float w  = ww_loc[i];
            float d  = s_dkr[n] + w*aekr;
            float nn = fmaxf(s_n2[n] + 2.f*w*s_dae[n] + w*w*ae2, 0.f);
            float cosv = __fdividef(d, fmaxf(sqrtf(nn)*nk, 1e-8f));
            float e = __expf(beta*cosv - beta);
            s_dkr[n]=e; lsum+=e;
        }
        const float invsum = __fdividef(1.f, bredsum1024(lsum, sred));
        #pragma unroll
        for (int i=0;i<8;i++){
            int n=t+i*1024;
            float wc = s_dkr[n]*invsum;
            s_dkr[n] = gg*wc + (1.f-gg)*wrp[base+n]*invs;
        }
        __syncthreads();
        float wp_loc[8];
        float lps=0.f;
        #pragma unroll
        for (int i=0;i<8;i++){
            int n=t+i*1024;
            float ws = s0*s_dkr[(n+NN-1)&(NN-1)] + s1*s_dkr[n] + s2*s_dkr[(n+1)&(NN-1)];
            float wp = __powf(ws, gamma);
            wp_loc[i]=wp; lps+=wp;
        }
        const float invp = __fdividef(1.f, bredsum1024(lps, sred));  // barrier: shift reads done
        float lS=0.f;
        #pragma unroll
        for (int i=0;i<8;i++){
            int n=t+i*1024;
            float w = wp_loc[i]*invp;
            s_dkr[n] = w;                 // s_dkr now holds w_r
            lS += ww_loc[i]*w;
        }
        S = bredsum1024(lS, sred);        // barrier: w_r visible
    }

    // ===================== weighted read =====================
    {
        const int sub16 = lane & 15;
        const int half = lane >> 4;
        float4 acc = make_float4(0.f,0.f,0.f,0.f);
        const float* bp = bank + base*MM + sub16*4;
        #pragma unroll 1
        for (int it=0; it<32; it++){
            float4 v[4]; float w4[4]; int row[4];
            #pragma unroll
            for (int j=0;j<4;j++){
                row[j] = (it*4+j)*64 + wid*2 + half;
                v[j] = *reinterpret_cast<const float4*>(bp + (size_t)row[j]*MM);
                w4[j] = s_dkr[row[j]];
            }
            #pragma unroll
            for (int j=0;j<4;j++){
                acc.x = fmaf(v[j].x, w4[j], acc.x);
                acc.y = fmaf(v[j].y, w4[j], acc.y);
                acc.z = fmaf(v[j].z, w4[j], acc.z);
                acc.w = fmaf(v[j].w, w4[j], acc.w);
            }
        }
        acc.x += __shfl_xor_sync(0xffffffffu, acc.x, 16);
        acc.y += __shfl_xor_sync(0xffffffffu, acc.y, 16);
        acc.z += __shfl_xor_sync(0xffffffffu, acc.z, 16);
        acc.w += __shfl_xor_sync(0xffffffffu, acc.w, 16);
        if (half == 0){
            atomicAdd(&scs[sub16*4+0], acc.x);
            atomicAdd(&scs[sub16*4+1], acc.y);
            atomicAdd(&scs[sub16*4+2], acc.z);
            atomicAdd(&scs[sub16*4+3], acc.w);
        }
        __syncthreads();
    }

    // ===================== final head =====================
    if (t < MM) om[t] = scs[t] + S*s_ae[t];
    __syncthreads();
    if (t < HID){
        float a = bsp[t];
        #pragma unroll 8
        for (int i=0;i<MM;i++) a = fmaf(om[i], Wsp[i*HID+t], a);
        seqs[t] = lrelu(a);
    }
    __syncthreads();
    if (t < SEQW){
        float a = bo[t];
        for (int i=0;i<HID;i++) a = fmaf(seqs[i], Wo[i*SEQW+t], a);
        out[b*SEQW+t] = 1.f/(1.f+__expf(-a));
    }
}

// ---------------- launch ----------------
extern "C" void kernel_launch(void* const* d_in, const int* in_sizes, int n_in,
                              void* d_out, int out_size)
{
    const float* x    = (const float*)d_in[0];
    const float* bank = (const float*)d_in[1];
    const float* wrp  = (const float*)d_in[2];
    const float* wwp  = (const float*)d_in[3];
    const float* W0   = (const float*)d_in[4];
    const float* b0   = (const float*)d_in[5];
    const float* W1   = (const float*)d_in[6];
    const float* b1   = (const float*)d_in[7];
    const float* Wc   = (const float*)d_in[8];
    const float* bc   = (const float*)d_in[9];
    const float* Wr   = (const float*)d_in[10];
    const float* br   = (const float*)d_in[11];
    const float* Ww   = (const float*)d_in[12];
    const float* bw   = (const float*)d_in[13];
    const float* Wea  = (const float*)d_in[14];
    const float* bea  = (const float*)d_in[15];
    const float* Wsp  = (const float*)d_in[16];
    const float* bsp  = (const float*)d_in[17];
    const float* Wo   = (const float*)d_in[18];
    const float* bo   = (const float*)d_in[19];
    float* out = (float*)d_out;

    cudaFuncSetAttribute(k_mega, cudaFuncAttributeMaxDynamicSharedMemorySize,
                         (int)SMEM_DYN);
    k_mega<<<BB, 1024, SMEM_DYN>>>(bank, x, wrp, wwp,
                                   W0,b0, W1,b1, Wc,bc, Wr,br, Ww,bw,
                                   Wea,bea, Wsp,bsp, Wo,bo, out);
}